// round 9
// baseline (speedup 1.0000x reference)
#include <cuda_runtime.h>
#include <cuda_fp16.h>

#define NMAX 100000
#define EMAX 1600000
#define CAP 96
#define LN_EPS 1e-5f

// ---------------- scratch (device globals: no allocation allowed) ----------
__device__ int   g_cursor[NMAX];
__device__ int   g_pad[(size_t)NMAX * CAP];           // padded adjacency (src ids)
__device__ __half g_xf[(size_t)NMAX * 16];            // fp16 padded node features
__device__ __half2 g_hx[(size_t)NMAX * 64];           // GEMM input activations
__device__ __half2 g_hy[(size_t)NMAX * 64];           // GEMM output / gather operand
__device__ __half  g_hW1[128 * 128];
__device__ __half  g_hW2[64 * 128];

// ---------------- helpers --------------------------------------------------
__device__ __forceinline__ unsigned smem_u32(const void* p) {
    unsigned a;
    asm("{ .reg .u64 t; cvta.to.shared.u64 t, %1; cvt.u32.u64 %0, t; }"
        : "=r"(a) : "l"(p));
    return a;
}
__device__ __forceinline__ void ldmx4(unsigned* r, unsigned addr) {
    asm volatile("ldmatrix.sync.aligned.m8n8.x4.shared.b16 {%0,%1,%2,%3}, [%4];"
                 : "=r"(r[0]), "=r"(r[1]), "=r"(r[2]), "=r"(r[3]) : "r"(addr));
}
__device__ __forceinline__ void mma16816(float* c, const unsigned* a, unsigned b0,
                                         unsigned b1) {
    asm volatile(
        "mma.sync.aligned.m16n8k16.row.col.f32.f16.f16.f32 "
        "{%0,%1,%2,%3},{%4,%5,%6,%7},{%8,%9},{%0,%1,%2,%3};"
        : "+f"(c[0]), "+f"(c[1]), "+f"(c[2]), "+f"(c[3])
        : "r"(a[0]), "r"(a[1]), "r"(a[2]), "r"(a[3]), "r"(b0), "r"(b1));
}
__device__ __forceinline__ void cpa16(unsigned dst, const void* src, bool valid) {
    int sz = valid ? 16 : 0;
    asm volatile("cp.async.cg.shared.global [%0], [%1], 16, %2;"
                 :: "r"(dst), "l"(src), "r"(sz));
}
__device__ __forceinline__ void cpa_commit() {
    asm volatile("cp.async.commit_group;");
}
__device__ __forceinline__ void cpa_wait1() {
    asm volatile("cp.async.wait_group 1;");
}
__device__ __forceinline__ float warp_sum(float v) {
#pragma unroll
    for (int o = 16; o; o >>= 1) v += __shfl_xor_sync(0xffffffffu, v, o);
    return v;
}

// ---------------- feature fp32 -> fp16 padded [N,16] -----------------------
__global__ void k_cvtX(const float* __restrict__ X, int n) {
    int i = blockIdx.x * 256 + threadIdx.x;
    if (i >= n) return;
    float v[16];
#pragma unroll
    for (int k = 0; k < 11; k++) v[k] = X[i * 11 + k];
#pragma unroll
    for (int k = 11; k < 16; k++) v[k] = 0.f;
    __half2 h[8];
#pragma unroll
    for (int k = 0; k < 8; k++) h[k] = __floats2half2_rn(v[2 * k], v[2 * k + 1]);
    uint4* o = (uint4*)&g_xf[(size_t)i * 16];
    o[0] = *(uint4*)&h[0];
    o[1] = *(uint4*)&h[4];
}

// ---------------- one-pass padded-CSR fill (4 edges/thread) ----------------
__global__ void k_fillpad(const int* __restrict__ src, const int* __restrict__ tgt,
                          int e) {
    int i = (blockIdx.x * blockDim.x + threadIdx.x) * 4;
    if (i + 3 < e) {
        int4 s = *(const int4*)&src[i];
        int4 t = *(const int4*)&tgt[i];
        int p0 = atomicAdd(&g_cursor[t.x], 1);
        if (p0 < CAP) g_pad[(size_t)t.x * CAP + p0] = s.x;
        int p1 = atomicAdd(&g_cursor[t.y], 1);
        if (p1 < CAP) g_pad[(size_t)t.y * CAP + p1] = s.y;
        int p2 = atomicAdd(&g_cursor[t.z], 1);
        if (p2 < CAP) g_pad[(size_t)t.z * CAP + p2] = s.z;
        int p3 = atomicAdd(&g_cursor[t.w], 1);
        if (p3 < CAP) g_pad[(size_t)t.w * CAP + p3] = s.w;
    } else {
        for (int k = i; k < e; k++) {
            int s = src[k], t = tgt[k];
            int p = atomicAdd(&g_cursor[t], 1);
            if (p < CAP) g_pad[(size_t)t * CAP + p] = s;
        }
    }
}

// ---------------- fused layer-0: gather + 11->128 GEMV + LN + ReLU ---------
__global__ void __launch_bounds__(256) k_l0(const float* __restrict__ W,
                                            const float* __restrict__ b,
                                            const float* __restrict__ gam,
                                            const float* __restrict__ bet,
                                            const float* __restrict__ W1,
                                            const float* __restrict__ W2,
                                            __half2* __restrict__ Yh, int n) {
    // side job: fp32->fp16 weight conversion for the MMA layers
    if (blockIdx.x < 64) {
        int i = blockIdx.x * 256 + threadIdx.x;
        g_hW1[i] = __float2half(W1[i]);
    } else if (blockIdx.x < 96) {
        int i = (blockIdx.x - 64) * 256 + threadIdx.x;
        g_hW2[i] = __float2half(W2[i]);
    }

    __shared__ float sW[128 * 11];
    __shared__ float sb[128], sg[128], sbe[128];
    int tid = threadIdx.x;
    for (int i = tid; i < 128 * 11; i += 256) sW[i] = W[i];
    if (tid < 128) { sb[tid] = b[tid]; sg[tid] = gam[tid]; sbe[tid] = bet[tid]; }
    __syncthreads();

    int warp = tid >> 5, lane = tid & 31;
    int node = blockIdx.x * 8 + warp;
    if (node >= n) return;
    int deg = g_cursor[node];
    int half = lane >> 4, f = lane & 15;
    int base = node * CAP;

    float acc = 0.f;
    for (int j = half; j < deg; j += 2) {
        int s = g_pad[base + j];
        acc += __half2float(g_xf[(size_t)s * 16 + f]);
    }
    acc += __shfl_xor_sync(0xffffffffu, acc, 16);
    float inv = 1.0f / (float)max(deg, 1);

    float fk[11];
#pragma unroll
    for (int k = 0; k < 11; k++)
        fk[k] = __shfl_sync(0xffffffffu, acc, k) * inv;

    int c0 = lane * 4;
    float a0 = sb[c0], a1 = sb[c0 + 1], a2 = sb[c0 + 2], a3 = sb[c0 + 3];
#pragma unroll
    for (int k = 0; k < 11; k++) {
        a0 += fk[k] * sW[(c0 + 0) * 11 + k];
        a1 += fk[k] * sW[(c0 + 1) * 11 + k];
        a2 += fk[k] * sW[(c0 + 2) * 11 + k];
        a3 += fk[k] * sW[(c0 + 3) * 11 + k];
    }
    if (deg == 0) { a0 = a1 = a2 = a3 = 0.f; }
    float mean = warp_sum(a0 + a1 + a2 + a3) * (1.0f / 128.0f);
    float d0 = a0 - mean, d1 = a1 - mean, d2 = a2 - mean, d3 = a3 - mean;
    float var = warp_sum(d0 * d0 + d1 * d1 + d2 * d2 + d3 * d3) * (1.0f / 128.0f);
    float rstd = rsqrtf(var + LN_EPS);
    float rx = fmaxf(d0 * rstd * sg[c0 + 0] + sbe[c0 + 0], 0.f);
    float ry = fmaxf(d1 * rstd * sg[c0 + 1] + sbe[c0 + 1], 0.f);
    float rz = fmaxf(d2 * rstd * sg[c0 + 2] + sbe[c0 + 2], 0.f);
    float rw = fmaxf(d3 * rstd * sg[c0 + 3] + sbe[c0 + 3], 0.f);
    __half2 h0 = __floats2half2_rn(rx, ry);
    __half2 h1 = __floats2half2_rn(rz, rw);
    uint2 u;
    u.x = *(unsigned*)&h0;
    u.y = *(unsigned*)&h1;
    *(uint2*)&Yh[(size_t)node * 64 + lane * 2] = u;
}

// ---------------- persistent weight-stationary pipelined tensor GEMM -------
// grid = NPERS CTAs. Each CTA stages W once, then loops over 128-row X tiles
// with a 2-deep cp.async pipeline: compute(tile t) overlaps load(tile t+2).
// smem stride 136 halfs (272B) keeps ldmatrix conflict-free.
#define NPERS 296
template <int NT>
__global__ void __launch_bounds__(256, 2) k_mma(const __half* __restrict__ X,
                                                const __half* __restrict__ Wh,
                                                const float* __restrict__ bias,
                                                __half2* __restrict__ Yh, int n) {
    const int WN = NT / 2;
    const int STR = 136;
    extern __shared__ __half dsm[];
    __half* sw = dsm;                       // NT x STR
    __half* sx0 = dsm + NT * STR;           // 128 x STR
    __half* sx1 = sx0 + 128 * STR;          // 128 x STR
    int tid = threadIdx.x, lane = tid & 31, wid = tid >> 5;
    int wy = wid >> 1, wx = wid & 1;
    int r8 = lane & 7, sub = lane >> 3;
    unsigned swb = smem_u32(sw);
    unsigned sxb[2] = {smem_u32(sx0), smem_u32(sx1)};

    int ntile = (n + 127) >> 7;

    // stage W (once per CTA)
#pragma unroll
    for (int it = 0; it < NT / 16; it++) {
        int idx = tid + it * 256;
        int r = idx >> 4, c16 = idx & 15;
        cpa16(swb + (r * STR + c16 * 8) * 2, &Wh[r * 128 + c16 * 8], true);
    }
    // prologue: load first two tiles
    {
        int t0 = blockIdx.x;
        int mB = t0 << 7;
        bool go = t0 < ntile;
#pragma unroll
        for (int it = 0; it < 8; it++) {
            int idx = tid + it * 256;
            int r = idx >> 4, c16 = idx & 15;
            int gm = mB + r;
            cpa16(sxb[0] + (r * STR + c16 * 8) * 2,
                  &X[(size_t)gm * 128 + c16 * 8], go && gm < n);
        }
        cpa_commit();   // group: W + tile0
        int t1 = t0 + NPERS;
        int mB1 = t1 << 7;
        bool go1 = t1 < ntile;
#pragma unroll
        for (int it = 0; it < 8; it++) {
            int idx = tid + it * 256;
            int r = idx >> 4, c16 = idx & 15;
            int gm = mB1 + r;
            cpa16(sxb[1] + (r * STR + c16 * 8) * 2,
                  &X[(size_t)gm * 128 + c16 * 8], go1 && gm < n);
        }
        cpa_commit();   // group: tile1
    }

    int buf = 0;
    for (int t = blockIdx.x; t < ntile; t += NPERS, buf ^= 1) {
        cpa_wait1();            // current tile (and W) landed
        __syncthreads();

        int mBase = t << 7;
        unsigned sxc = sxb[buf];

        float c[2][WN / 8][4];
#pragma unroll
        for (int mi = 0; mi < 2; mi++)
#pragma unroll
            for (int nb = 0; nb < WN / 8; nb++)
#pragma unroll
                for (int q = 0; q < 4; q++) c[mi][nb][q] = 0.f;

#pragma unroll
        for (int ks = 0; ks < 8; ks++) {
            int k0 = ks * 16;
            unsigned a[2][4];
#pragma unroll
            for (int mi = 0; mi < 2; mi++) {
                int row = wy * 32 + mi * 16 + r8 + ((sub & 1) << 3);
                int kof = k0 + ((sub >> 1) << 3);
                ldmx4(a[mi], sxc + (row * STR + kof) * 2);
            }
            unsigned bf[WN / 8][2];
#pragma unroll
            for (int nb = 0; nb < WN / 16; nb++) {
                int n0 = wx * WN + nb * 16;
                int row = n0 + r8 + ((sub >> 1) << 3);
                int kof = k0 + ((sub & 1) << 3);
                unsigned t4[4];
                ldmx4(t4, swb + (row * STR + kof) * 2);
                bf[2 * nb][0] = t4[0];
                bf[2 * nb][1] = t4[1];
                bf[2 * nb + 1][0] = t4[2];
                bf[2 * nb + 1][1] = t4[3];
            }
#pragma unroll
            for (int mi = 0; mi < 2; mi++)
#pragma unroll
                for (int nb = 0; nb < WN / 8; nb++)
                    mma16816(c[mi][nb], a[mi], bf[nb][0], bf[nb][1]);
        }
        __syncthreads();        // all warps done reading buf before refill

        // refill this buffer with tile t + 2*NPERS
        {
            int t2 = t + 2 * NPERS;
            int mB2 = t2 << 7;
            bool go2 = t2 < ntile;
#pragma unroll
            for (int it = 0; it < 8; it++) {
                int idx = tid + it * 256;
                int r = idx >> 4, c16 = idx & 15;
                int gm = mB2 + r;
                cpa16(sxc + (r * STR + c16 * 8) * 2,
                      &X[(size_t)gm * 128 + c16 * 8], go2 && gm < n);
            }
            cpa_commit();
        }

        // epilogue: bias + fp16 store
        int g = lane >> 2, tt = lane & 3;
#pragma unroll
        for (int mi = 0; mi < 2; mi++) {
            int row0 = mBase + wy * 32 + mi * 16 + g;
#pragma unroll
            for (int nb = 0; nb < WN / 8; nb++) {
                int col = wx * WN + nb * 8 + 2 * tt;
                float2 bv = *(const float2*)&bias[col];
                if (row0 < n) {
                    __half2 h = __floats2half2_rn(c[mi][nb][0] + bv.x,
                                                  c[mi][nb][1] + bv.y);
                    Yh[(size_t)row0 * (NT / 2) + (col >> 1)] = h;
                }
                int row1 = row0 + 8;
                if (row1 < n) {
                    __half2 h = __floats2half2_rn(c[mi][nb][2] + bv.x,
                                                  c[mi][nb][3] + bv.y);
                    Yh[(size_t)row1 * (NT / 2) + (col >> 1)] = h;
                }
            }
        }
    }
}

// ---------------- fused aggregate (fp16 in) + deg-norm + LN (+ReLU) --------
__device__ __forceinline__ void acc_row128(float* acc, const __half2* __restrict__ X,
                                           int s, int lane) {
    uint2 u = *(const uint2*)&X[(size_t)s * 64 + lane * 2];
    __half2 h0 = *(__half2*)&u.x, h1 = *(__half2*)&u.y;
    float2 f0 = __half22float2(h0), f1 = __half22float2(h1);
    acc[0] += f0.x; acc[1] += f0.y; acc[2] += f1.x; acc[3] += f1.y;
}

template <int HD, bool RELU, bool HOUT>
__global__ void k_agg_ln(const __half2* __restrict__ XT, const float* __restrict__ gam,
                         const float* __restrict__ bet, void* __restrict__ out, int n) {
    int gw = (blockIdx.x * blockDim.x + threadIdx.x) >> 5;
    int lane = threadIdx.x & 31;
    if (gw >= n) return;
    int deg = g_cursor[gw];
    int rs = gw * CAP, re = rs + deg;
    const int V = HD / 32;
    float acc[V];
#pragma unroll
    for (int i = 0; i < V; i++) acc[i] = 0.f;

    int e = rs;
    if constexpr (V == 4) {
        for (; e + 3 < re; e += 4) {
            int s0 = g_pad[e + 0], s1 = g_pad[e + 1];
            int s2 = g_pad[e + 2], s3 = g_pad[e + 3];
            acc_row128(acc, XT, s0, lane);
            acc_row128(acc, XT, s1, lane);
            acc_row128(acc, XT, s2, lane);
            acc_row128(acc, XT, s3, lane);
        }
        for (; e < re; e++) acc_row128(acc, XT, g_pad[e], lane);
    } else {
        for (; e + 3 < re; e += 4) {
            int s0 = g_pad[e + 0], s1 = g_pad[e + 1];
            int s2 = g_pad[e + 2], s3 = g_pad[e + 3];
            float2 f0 = __half22float2(XT[(size_t)s0 * 32 + lane]);
            float2 f1 = __half22float2(XT[(size_t)s1 * 32 + lane]);
            float2 f2 = __half22float2(XT[(size_t)s2 * 32 + lane]);
            float2 f3 = __half22float2(XT[(size_t)s3 * 32 + lane]);
            acc[0] += (f0.x + f1.x) + (f2.x + f3.x);
            acc[1] += (f0.y + f1.y) + (f2.y + f3.y);
        }
        for (; e < re; e++) {
            float2 f0 = __half22float2(XT[(size_t)g_pad[e] * 32 + lane]);
            acc[0] += f0.x; acc[1] += f0.y;
        }
    }

    float inv = 1.0f / (float)(deg > 0 ? deg : 1);
    float v[V];
    float psum = 0.f;
#pragma unroll
    for (int i = 0; i < V; i++) { v[i] = acc[i] * inv; psum += v[i]; }
    float mean = warp_sum(psum) * (1.0f / (float)HD);
    float d[V];
    float ps2 = 0.f;
#pragma unroll
    for (int i = 0; i < V; i++) { d[i] = v[i] - mean; ps2 += d[i] * d[i]; }
    float var = warp_sum(ps2) * (1.0f / (float)HD);
    float rstd = rsqrtf(var + LN_EPS);

    if constexpr (V == 4) {
        float4 G = *(const float4*)&gam[lane * 4];
        float4 B = *(const float4*)&bet[lane * 4];
        float rx = d[0] * rstd * G.x + B.x;
        float ry = d[1] * rstd * G.y + B.y;
        float rz = d[2] * rstd * G.z + B.z;
        float rw = d[3] * rstd * G.w + B.w;
        if (RELU) {
            rx = fmaxf(rx, 0.f); ry = fmaxf(ry, 0.f);
            rz = fmaxf(rz, 0.f); rw = fmaxf(rw, 0.f);
        }
        if constexpr (HOUT) {
            __half2 h0 = __floats2half2_rn(rx, ry);
            __half2 h1 = __floats2half2_rn(rz, rw);
            uint2 u;
            u.x = *(unsigned*)&h0;
            u.y = *(unsigned*)&h1;
            *(uint2*)&((__half2*)out)[(size_t)gw * 64 + lane * 2] = u;
        } else {
            float4 r = make_float4(rx, ry, rz, rw);
            *(float4*)&((float*)out)[(size_t)gw * HD + lane * 4] = r;
        }
    } else {
        float2 G = *(const float2*)&gam[lane * 2];
        float2 B = *(const float2*)&bet[lane * 2];
        float2 r;
        r.x = d[0] * rstd * G.x + B.x;
        r.y = d[1] * rstd * G.y + B.y;
        if (RELU) { r.x = fmaxf(r.x, 0.f); r.y = fmaxf(r.y, 0.f); }
        *(float2*)&((float*)out)[(size_t)gw * HD + lane * 2] = r;
    }
}

// ---------------- launcher -------------------------------------------------
extern "C" void kernel_launch(void* const* d_in, const int* in_sizes, int n_in,
                              void* d_out, int out_size) {
    const float* nf  = (const float*)d_in[0];
    const int*   ei  = (const int*)d_in[1];
    const float* W0  = (const float*)d_in[2];
    const float* b0  = (const float*)d_in[3];
    const float* W1  = (const float*)d_in[4];
    const float* b1  = (const float*)d_in[5];
    const float* W2  = (const float*)d_in[6];
    const float* b2  = (const float*)d_in[7];
    const float* g0  = (const float*)d_in[8];
    const float* be0 = (const float*)d_in[9];
    const float* g1  = (const float*)d_in[10];
    const float* be1 = (const float*)d_in[11];
    const float* g2  = (const float*)d_in[12];
    const float* be2 = (const float*)d_in[13];

    int n = in_sizes[0] / 11;
    int e = in_sizes[1] / 2;
    const int* src = ei;
    const int* tgt = ei + e;

    __half2 *hX, *hY;
    __half *hW1, *hW2;
    int* curp;
    cudaGetSymbolAddress((void**)&hX, g_hx);
    cudaGetSymbolAddress((void**)&hY, g_hy);
    cudaGetSymbolAddress((void**)&hW1, g_hW1);
    cudaGetSymbolAddress((void**)&hW2, g_hW2);
    cudaGetSymbolAddress((void**)&curp, g_cursor);

    const int SMEM128 = (128 + 2 * 128) * 136 * 2;   // 104448
    const int SMEM64  = (64 + 2 * 128) * 136 * 2;    // 87040
    cudaFuncSetAttribute(k_mma<128>, cudaFuncAttributeMaxDynamicSharedMemorySize,
                         SMEM128);
    cudaFuncSetAttribute(k_mma<64>, cudaFuncAttributeMaxDynamicSharedMemorySize,
                         SMEM64);

    // padded-CSR build + feature conversion
    cudaMemsetAsync(curp, 0, n * sizeof(int));
    k_cvtX<<<(n + 255) / 256, 256>>>(nf, n);
    k_fillpad<<<(e / 4 + 255) / 256, 256>>>(src, tgt, e);

    // layer 0: fused gather + GEMV + LN + ReLU (also converts W1/W2 to fp16)
    k_l0<<<(n + 7) / 8, 256>>>(W0, b0, g0, be0, W1, W2, hX, n);

    // layer 1: 128 -> 128 (persistent pipelined tensor cores)
    k_mma<128><<<NPERS, 256, SMEM128>>>((const __half*)hX, hW1, b1, hY, n);
    k_agg_ln<128, true, true><<<(n + 7) / 8, 256>>>(hY, g1, be1, hX, n);

    // layer 2: 128 -> 64 (persistent pipelined tensor cores)
    k_mma<64><<<NPERS, 256, SMEM64>>>((const __half*)hX, hW2, b2, hY, n);
    k_agg_ln<64, false, false><<<(n + 7) / 8, 256>>>(hY, g2, be2, d_out, n);
}